// round 1
// baseline (speedup 1.0000x reference)
#include <cuda_runtime.h>

#define N_NODES 100000
#define F_IN 256
#define CH 16
#define NL 7
#define CH2 8   // NL padded to 8 for float4 atomics

// ---------------- scratch (static device memory; no allocs) ----------------
__device__ __align__(128) float g_hs  [N_NODES * CH];   // layer1 pre-scaled transform
__device__ __align__(128) float g_out1[N_NODES * CH];   // layer1 accumulator
__device__ __align__(128) float g_hs2 [N_NODES * CH2];  // layer2 pre-scaled transform (padded)
__device__ __align__(128) float g_out2[N_NODES * CH2];  // layer2 accumulator (padded)
__device__ float g_dinv[N_NODES];
__device__ int   g_deg [N_NODES];

// vector float4 reduction (no return) — sm_90+: red.global.add.v4.f32
__device__ __forceinline__ void red_add_f32x4(float* p, float a, float b, float c, float d) {
    asm volatile("red.global.add.v4.f32 [%0], {%1, %2, %3, %4};"
                 :: "l"(p), "f"(a), "f"(b), "f"(c), "f"(d) : "memory");
}

// ---------------- degree / norm ----------------
__global__ void k_init_deg() {
    int i = blockIdx.x * blockDim.x + threadIdx.x;
    if (i < N_NODES) g_deg[i] = 1;   // self loop
}

__global__ void k_deg(const int* __restrict__ dst, int E) {
    int i = blockIdx.x * blockDim.x + threadIdx.x;
    if (i < E) atomicAdd(&g_deg[dst[i]], 1);
}

__global__ void k_dinv() {
    int i = blockIdx.x * blockDim.x + threadIdx.x;
    if (i < N_NODES) g_dinv[i] = rsqrtf((float)g_deg[i]);
}

// ---------------- GEMM1: hs = (x @ W0) * dinv, also init out1 ----------------
// Block: 128 threads = 8 row-groups x 16 cols, tile = 32 rows, full K=256 staged.
// Static smem = 32*256*4 + 256*16*4 = 32768 + 16384 = 49152 B (exactly 48KB).
#define GROWS 32
__global__ void __launch_bounds__(128) k_gemm1(const float* __restrict__ x,
                                               const float* __restrict__ W0) {
    __shared__ float xs[GROWS][F_IN];
    __shared__ float W0s[F_IN * CH];
    const int tid  = threadIdx.x;
    const int row0 = blockIdx.x * GROWS;

    // stage W0: 4096 floats = 1024 float4, 8 per thread
    #pragma unroll
    for (int i = 0; i < 8; i++) {
        ((float4*)W0s)[tid + 128 * i] = ((const float4*)W0)[tid + 128 * i];
    }
    // stage x tile: 32 rows * 64 float4 = 2048 float4, 16 per thread (coalesced)
    #pragma unroll
    for (int i = 0; i < 16; i++) {
        int f  = tid + 128 * i;
        int r  = f >> 6;       // / 64
        int k4 = f & 63;
        int row = row0 + r;
        float4 v = make_float4(0.f, 0.f, 0.f, 0.f);
        if (row < N_NODES) v = ((const float4*)(x + (size_t)row * F_IN))[k4];
        ((float4*)&xs[r][0])[k4] = v;
    }
    __syncthreads();

    const int rg = tid >> 4;   // 0..7 (row group of 4 rows)
    const int j  = tid & 15;   // output column

    float acc0 = 0.f, acc1 = 0.f, acc2 = 0.f, acc3 = 0.f;
    #pragma unroll 4
    for (int k = 0; k < F_IN; k += 4) {
        float w0 = W0s[(k + 0) * CH + j];
        float w1 = W0s[(k + 1) * CH + j];
        float w2 = W0s[(k + 2) * CH + j];
        float w3 = W0s[(k + 3) * CH + j];
        float4 v;
        v = *(const float4*)&xs[rg * 4 + 0][k];
        acc0 += v.x * w0 + v.y * w1 + v.z * w2 + v.w * w3;
        v = *(const float4*)&xs[rg * 4 + 1][k];
        acc1 += v.x * w0 + v.y * w1 + v.z * w2 + v.w * w3;
        v = *(const float4*)&xs[rg * 4 + 2][k];
        acc2 += v.x * w0 + v.y * w1 + v.z * w2 + v.w * w3;
        v = *(const float4*)&xs[rg * 4 + 3][k];
        acc3 += v.x * w0 + v.y * w1 + v.z * w2 + v.w * w3;
    }

    float accs[4] = {acc0, acc1, acc2, acc3};
    #pragma unroll
    for (int r = 0; r < 4; r++) {
        int row = row0 + rg * 4 + r;
        if (row < N_NODES) {
            float v = accs[r] * g_dinv[row];
            g_hs  [row * CH + j] = v;
            g_out1[row * CH + j] = v;   // self-loop contribution
        }
    }
}

// ---------------- edge scatter, layer 1 (16 floats/row, 4 threads/edge) ----------------
__global__ void k_edge1(const int* __restrict__ src, const int* __restrict__ dst, int E) {
    int t = blockIdx.x * blockDim.x + threadIdx.x;
    if (t >= 4 * E) return;
    int e = t >> 2;
    int c = t & 3;
    int s = src[e];
    int d = dst[e];
    float4 v = ((const float4*)(g_hs + (size_t)s * CH))[c];
    red_add_f32x4((float*)(((float4*)(g_out1 + (size_t)d * CH)) + c), v.x, v.y, v.z, v.w);
}

// ---------------- mid: h1 = relu(out1*dinv); hs2 = (h1 @ W1)*dinv; init out2 ----------
__global__ void __launch_bounds__(256) k_mid(const float* __restrict__ W1) {
    __shared__ float W1s[CH * NL];
    if (threadIdx.x < CH * NL) W1s[threadIdx.x] = W1[threadIdx.x];
    __syncthreads();

    int t = blockIdx.x * blockDim.x + threadIdx.x;
    int row0 = t * 4;
    if (row0 >= N_NODES) return;   // N_NODES divisible by 4

    float h[4][CH];
    float di[4];
    #pragma unroll
    for (int r = 0; r < 4; r++) {
        int row = row0 + r;
        di[r] = g_dinv[row];
        #pragma unroll
        for (int q = 0; q < 4; q++) {
            float4 v = *(const float4*)(g_out1 + (size_t)row * CH + q * 4);
            h[r][q * 4 + 0] = fmaxf(v.x * di[r], 0.f);
            h[r][q * 4 + 1] = fmaxf(v.y * di[r], 0.f);
            h[r][q * 4 + 2] = fmaxf(v.z * di[r], 0.f);
            h[r][q * 4 + 3] = fmaxf(v.w * di[r], 0.f);
        }
    }

    float acc[4][NL];
    #pragma unroll
    for (int r = 0; r < 4; r++)
        #pragma unroll
        for (int c = 0; c < NL; c++) acc[r][c] = 0.f;

    #pragma unroll
    for (int jj = 0; jj < CH; jj++) {
        #pragma unroll
        for (int c = 0; c < NL; c++) {
            float w = W1s[jj * NL + c];
            #pragma unroll
            for (int r = 0; r < 4; r++) acc[r][c] += h[r][jj] * w;
        }
    }

    #pragma unroll
    for (int r = 0; r < 4; r++) {
        int row = row0 + r;
        float4 lo = make_float4(acc[r][0] * di[r], acc[r][1] * di[r],
                                acc[r][2] * di[r], acc[r][3] * di[r]);
        float4 hi = make_float4(acc[r][4] * di[r], acc[r][5] * di[r],
                                acc[r][6] * di[r], 0.f);
        *(float4*)(g_hs2  + (size_t)row * CH2)     = lo;
        *(float4*)(g_hs2  + (size_t)row * CH2 + 4) = hi;
        *(float4*)(g_out2 + (size_t)row * CH2)     = lo;   // self loop
        *(float4*)(g_out2 + (size_t)row * CH2 + 4) = hi;
    }
}

// ---------------- edge scatter, layer 2 (8 floats/row padded, 2 threads/edge) ----------
__global__ void k_edge2(const int* __restrict__ src, const int* __restrict__ dst, int E) {
    int t = blockIdx.x * blockDim.x + threadIdx.x;
    if (t >= 2 * E) return;
    int e = t >> 1;
    int c = t & 1;
    int s = src[e];
    int d = dst[e];
    float4 v = ((const float4*)(g_hs2 + (size_t)s * CH2))[c];
    red_add_f32x4((float*)(((float4*)(g_out2 + (size_t)d * CH2)) + c), v.x, v.y, v.z, v.w);
}

// ---------------- finalize: out = exp(out2*dinv) + 1 ----------------
__global__ void k_final(float* __restrict__ out) {
    int t = blockIdx.x * blockDim.x + threadIdx.x;
    if (t >= N_NODES * NL) return;
    int i = t / NL;
    int j = t - i * NL;
    out[t] = expf(g_out2[(size_t)i * CH2 + j] * g_dinv[i]) + 1.0f;
}

// ---------------- launch ----------------
extern "C" void kernel_launch(void* const* d_in, const int* in_sizes, int n_in,
                              void* d_out, int out_size) {
    const float* x  = (const float*)d_in[0];
    const float* W0 = (const float*)d_in[1];
    const float* W1 = (const float*)d_in[2];
    const int*   ei = (const int*)d_in[3];
    const int E = in_sizes[3] / 2;
    const int* src = ei;
    const int* dst = ei + E;
    float* out = (float*)d_out;

    k_init_deg<<<(N_NODES + 255) / 256, 256>>>();
    k_deg<<<(E + 255) / 256, 256>>>(dst, E);
    k_dinv<<<(N_NODES + 255) / 256, 256>>>();

    k_gemm1<<<(N_NODES + GROWS - 1) / GROWS, 128>>>(x, W0);

    k_edge1<<<(4 * E + 255) / 256, 256>>>(src, dst, E);

    k_mid<<<(N_NODES / 4 + 255) / 256, 256>>>(W1);

    k_edge2<<<(2 * E + 255) / 256, 256>>>(src, dst, E);

    k_final<<<(N_NODES * NL + 255) / 256, 256>>>(out);
}